// round 8
// baseline (speedup 1.0000x reference)
#include <cuda_runtime.h>
#include <cstdint>

// PermutationInvariantNet: B=8, N=256, IN_DIM=2, D=128, H=512, L=2
// Tokens T = B*N = 2048. fp32.
// 7 launches: embed, 2x { stats, pool_gemm+LN, ff(ff1+relu+ff2+res+LN) }.
// GEMM cores: RR=4 register blocking (thread = 4 rows x 2 cols), cp.async
// weight pipelining, warp+smem LayerNorm epilogues.

#define T_TOK 2048
#define NB 8
#define NN 256
#define DD 128
#define HH 512
#define LN_EPS 1e-5f
#define NEG_INF -3.402823466e38f

// -------- scratch (device globals; no allocation allowed) --------
__device__ __align__(16) float g_h[T_TOK * DD];   // hidden state (1 MB)
__device__ float g_m1[NB * DD];                   // per-batch per-feature max
__device__ float g_m2[NB * DD];                   // second max
__device__ int   g_i1[NB * DD];                   // argmax (n within batch)

// -------- cp.async helpers --------
__device__ __forceinline__ void cp_async16(uint32_t dst, const void* src) {
    asm volatile("cp.async.cg.shared.global [%0], [%1], 16;" :: "r"(dst), "l"(src));
}
__device__ __forceinline__ void cp_commit() {
    asm volatile("cp.async.commit_group;");
}
__device__ __forceinline__ void cp_wait1() {
    asm volatile("cp.async.wait_group 1;");
}
__device__ __forceinline__ void cp_wait0() {
    asm volatile("cp.async.wait_group 0;");
}

// -------- block LayerNorm over 128 threads (embed kernel only) --------
__device__ __forceinline__ void ln_stats_128(float y, float& mean, float& rstd) {
    __shared__ float sh[8];
    float s = y, q = y * y;
#pragma unroll
    for (int o = 16; o > 0; o >>= 1) {
        s += __shfl_xor_sync(0xffffffffu, s, o);
        q += __shfl_xor_sync(0xffffffffu, q, o);
    }
    int lane = threadIdx.x & 31, w = threadIdx.x >> 5;
    if (lane == 0) { sh[w] = s; sh[4 + w] = q; }
    __syncthreads();
    s = sh[0] + sh[1] + sh[2] + sh[3];
    q = sh[4] + sh[5] + sh[6] + sh[7];
    mean = s * (1.0f / DD);
    float var = q * (1.0f / DD) - mean * mean;
    rstd = rsqrtf(var + LN_EPS);
}

// -------- embed + LN:  h = LN(x @ We + be) --------
__global__ void __launch_bounds__(128)
embed_ln_kernel(const float* __restrict__ x, const float* __restrict__ We,
                const float* __restrict__ be, const float* __restrict__ ge,
                const float* __restrict__ bge) {
    int t = blockIdx.x, d = threadIdx.x;
    float x0 = x[t * 2 + 0];
    float x1 = x[t * 2 + 1];
    float y = fmaf(x0, We[d], fmaf(x1, We[DD + d], be[d]));
    float mean, rstd;
    ln_stats_128(y, mean, rstd);
    g_h[t * DD + d] = (y - mean) * rstd * ge[d] + bge[d];
}

// -------- per-batch per-feature (max1, max2, argmax) over N=256 --------
__global__ void __launch_bounds__(512)
stats_kernel() {
    int b = blockIdx.x;
    int d = threadIdx.x;
    int s = threadIdx.y;
    const float* hb = g_h + b * NN * DD;

    float m1 = NEG_INF, m2 = NEG_INF;
    int i1 = 0;
    int n0 = s * (NN / 4);
#pragma unroll 8
    for (int n = n0; n < n0 + NN / 4; n++) {
        float v = hb[n * DD + d];
        if (v > m1) { m2 = m1; m1 = v; i1 = n; }
        else if (v > m2) { m2 = v; }
    }
    __shared__ float sm1[4][DD], sm2[4][DD];
    __shared__ int si1[4][DD];
    sm1[s][d] = m1; sm2[s][d] = m2; si1[s][d] = i1;
    __syncthreads();
    if (s == 0) {
#pragma unroll
        for (int j = 1; j < 4; j++) {
            float a1 = sm1[j][d], a2 = sm2[j][d];
            int ai = si1[j][d];
            if (a1 > m1) { m2 = fmaxf(m1, a2); m1 = a1; i1 = ai; }
            else         { m2 = fmaxf(m2, a1); }
        }
        g_m1[b * DD + d] = m1;
        g_m2[b * DD + d] = m2;
        g_i1[b * DD + d] = i1;
    }
}

// ===================== pool GEMM (+res+LN) =====================
// h = LN(h + [h, loo(h)] @ Wp + bp). Block: 256 thr = 8 warps =
// 4 rowgrps x 2 colgrps; thread owns 4 rows x 2 cols. K=256.
// Wp (128KB) loaded via cp.async in 2 halves (2nd overlaps 1st's compute).
// smem floats: As[16][256]=4096 | Ws[256][128]=32768 | lnS/Q 64
#define POOL_SMEM ((4096 + 32768 + 64) * 4)
__global__ void __launch_bounds__(256, 1)
pool_gemm_ln_kernel(const float* __restrict__ Wp, const float* __restrict__ bp,
                    const float* __restrict__ gp, const float* __restrict__ bgp) {
    extern __shared__ float smem[];
    float (*As)[256] = reinterpret_cast<float (*)[256]>(smem);
    float (*Ws)[DD]  = reinterpret_cast<float (*)[DD]>(smem + 4096);
    float (*lnS)[16] = reinterpret_cast<float (*)[16]>(smem + 4096 + 32768);
    float (*lnQ)[16] = reinterpret_cast<float (*)[16]>(smem + 4096 + 32768 + 32);

    const int tid = threadIdx.x;
    const int lane = tid & 31, wid = tid >> 5;
    const int rg = wid & 3, cg = wid >> 2;
    const int rg4 = rg * 4;
    const int c2 = cg * 64 + lane * 2;
    const int row0 = blockIdx.x * 16;
    const int b = row0 >> 8;
    const int nbase = row0 & 255;

    // issue Wp loads: 2 halves of 128 k-rows, 16 cp.async each per thread
    uint32_t ws_base = (uint32_t)__cvta_generic_to_shared(&Ws[0][0]);
#pragma unroll
    for (int h = 0; h < 2; h++) {
#pragma unroll
        for (int i = 0; i < 16; i++) {
            int t16 = tid + i * 256;            // 0..4095
            int k = h * 128 + (t16 >> 5);
            int c4 = (t16 & 31) << 2;
            cp_async16(ws_base + (uint32_t)(k * DD + c4) * 4, Wp + k * DD + c4);
        }
        cp_commit();
    }

    // fill As: h part (cols 0..127) + synthesized pooled part (cols 128..255)
#pragma unroll
    for (int i = 0; i < 2; i++) {
        int idx4 = (tid + i * 256) * 4;
        int r = idx4 >> 7, k = idx4 & 127;
        *reinterpret_cast<float4*>(&As[r][k]) =
            *reinterpret_cast<const float4*>(&g_h[row0 * DD + idx4]);
    }
#pragma unroll
    for (int i = 0; i < 8; i++) {
        int idx = tid + i * 256;                // 0..2047
        int r = idx >> 7, k = idx & 127;
        int am = g_i1[b * DD + k];
        float m1 = g_m1[b * DD + k], m2 = g_m2[b * DD + k];
        As[r][128 + k] = (nbase + r == am) ? m2 : m1;
    }

    float acc[4][2];
#pragma unroll
    for (int r = 0; r < 4; r++) { acc[r][0] = 0.f; acc[r][1] = 0.f; }

    cp_wait1();          // first half of Wp ready
    __syncthreads();     // + As visible

#pragma unroll 4
    for (int k0 = 0; k0 < 128; k0 += 4) {
        float a[4][4];
#pragma unroll
        for (int r = 0; r < 4; r++)
            *reinterpret_cast<float4*>(a[r]) =
                *reinterpret_cast<const float4*>(&As[rg4 + r][k0]);
#pragma unroll
        for (int kk = 0; kk < 4; kk++) {
            float2 w = *reinterpret_cast<const float2*>(&Ws[k0 + kk][c2]);
#pragma unroll
            for (int r = 0; r < 4; r++) {
                acc[r][0] = fmaf(a[r][kk], w.x, acc[r][0]);
                acc[r][1] = fmaf(a[r][kk], w.y, acc[r][1]);
            }
        }
    }

    cp_wait0();          // second half ready
    __syncthreads();

#pragma unroll 4
    for (int k0 = 128; k0 < 256; k0 += 4) {
        float a[4][4];
#pragma unroll
        for (int r = 0; r < 4; r++)
            *reinterpret_cast<float4*>(a[r]) =
                *reinterpret_cast<const float4*>(&As[rg4 + r][k0]);
#pragma unroll
        for (int kk = 0; kk < 4; kk++) {
            float2 w = *reinterpret_cast<const float2*>(&Ws[k0 + kk][c2]);
#pragma unroll
            for (int r = 0; r < 4; r++) {
                acc[r][0] = fmaf(a[r][kk], w.x, acc[r][0]);
                acc[r][1] = fmaf(a[r][kk], w.y, acc[r][1]);
            }
        }
    }

    // epilogue: +bias +residual (As h-part), LN (warp partial + 2-way combine)
    float v[4][2], s[4], q[4];
    float bp0 = bp[c2], bp1 = bp[c2 + 1];
#pragma unroll
    for (int r = 0; r < 4; r++) {
        v[r][0] = acc[r][0] + bp0 + As[rg4 + r][c2];
        v[r][1] = acc[r][1] + bp1 + As[rg4 + r][c2 + 1];
        s[r] = v[r][0] + v[r][1];
        q[r] = v[r][0] * v[r][0] + v[r][1] * v[r][1];
    }
#pragma unroll
    for (int o = 16; o > 0; o >>= 1)
#pragma unroll
        for (int r = 0; r < 4; r++) {
            s[r] += __shfl_xor_sync(0xffffffffu, s[r], o);
            q[r] += __shfl_xor_sync(0xffffffffu, q[r], o);
        }
    if (lane == 0)
#pragma unroll
        for (int r = 0; r < 4; r++) { lnS[cg][rg4 + r] = s[r]; lnQ[cg][rg4 + r] = q[r]; }
    __syncthreads();
    float g0 = gp[c2], g1 = gp[c2 + 1], e0 = bgp[c2], e1 = bgp[c2 + 1];
#pragma unroll
    for (int r = 0; r < 4; r++) {
        float S = lnS[0][rg4 + r] + lnS[1][rg4 + r];
        float Q = lnQ[0][rg4 + r] + lnQ[1][rg4 + r];
        float mean = S * (1.0f / DD);
        float rstd = rsqrtf(Q * (1.0f / DD) - mean * mean + LN_EPS);
        float2 o;
        o.x = (v[r][0] - mean) * rstd * g0 + e0;
        o.y = (v[r][1] - mean) * rstd * g1 + e1;
        *reinterpret_cast<float2*>(&g_h[(row0 + rg4 + r) * DD + c2]) = o;
    }
}

// ===================== fused FF =====================
// h' = LN(h + relu(h@W1+b1)@W2 + b2). 4 H-chunks of 128.
// smem floats: hs[16][128]=2048 | W1c[2][128][128]=32768 | W2c[128][128]=16384
//              | Us[16][128]=2048 | lnS/Q 64  -> 213504 B
#define FF_SMEM ((2048 + 32768 + 16384 + 2048 + 64) * 4)
template <bool FINAL>
__global__ void __launch_bounds__(256, 1)
ff_fused_kernel(const float* __restrict__ W1, const float* __restrict__ b1,
                const float* __restrict__ W2, const float* __restrict__ b2,
                const float* __restrict__ gf, const float* __restrict__ bgf,
                float* __restrict__ out) {
    extern __shared__ float smem[];
    float (*hs)[DD]  = reinterpret_cast<float (*)[DD]>(smem);                  // 16x128
    float* W1c       = smem + 2048;                                            // [2][128][128]
    float (*W2c)[DD] = reinterpret_cast<float (*)[DD]>(smem + 2048 + 32768);   // 128x128
    float (*Us)[DD]  = reinterpret_cast<float (*)[DD]>(smem + 2048 + 32768 + 16384);
    float (*lnS)[16] = reinterpret_cast<float (*)[16]>(smem + 2048 + 32768 + 16384 + 2048);
    float (*lnQ)[16] = reinterpret_cast<float (*)[16]>(smem + 2048 + 32768 + 16384 + 2048 + 32);

    const int tid = threadIdx.x;
    const int lane = tid & 31, wid = tid >> 5;
    const int rg = wid & 3, cg = wid >> 2;
    const int rg4 = rg * 4;
    const int c2 = cg * 64 + lane * 2;
    const int row0 = blockIdx.x * 16;

    const uint32_t w1s = (uint32_t)__cvta_generic_to_shared(W1c);
    const uint32_t w2s = (uint32_t)__cvta_generic_to_shared(&W2c[0][0]);

    // issue chunk-0 weight loads immediately
    {
#pragma unroll
        for (int i = 0; i < 16; i++) {           // W1 chunk 0 -> buf 0
            int t16 = tid + i * 256;
            int k = t16 >> 5, c4 = (t16 & 31) << 2;
            cp_async16(w1s + (uint32_t)(k * DD + c4) * 4, W1 + k * HH + c4);
        }
        cp_commit();
#pragma unroll
        for (int i = 0; i < 16; i++) {           // W2 chunk 0
            int t16 = tid + i * 256;
            int k = t16 >> 5, c4 = (t16 & 31) << 2;
            cp_async16(w2s + (uint32_t)(k * DD + c4) * 4, W2 + k * DD + c4);
        }
        cp_commit();
    }

    // load h rows (doubles as residual)
#pragma unroll
    for (int i = 0; i < 2; i++) {
        int idx4 = (tid + i * 256) * 4;
        *reinterpret_cast<float4*>(&hs[idx4 >> 7][idx4 & 127]) =
            *reinterpret_cast<const float4*>(&g_h[row0 * DD + idx4]);
    }

    float acc2[4][2];
#pragma unroll
    for (int r = 0; r < 4; r++) { acc2[r][0] = 0.f; acc2[r][1] = 0.f; }

    for (int ci = 0; ci < 4; ci++) {
        const int c0 = ci * 128;
        const float* W1b = W1c + (ci & 1) * 16384;

        cp_wait1();          // W1(ci) ready (W2(ci) may still fly)
        __syncthreads();     // + hs/Us hazards

        // ---- ff1: acc1 = hs @ W1b ----
        float acc1[4][2];
#pragma unroll
        for (int r = 0; r < 4; r++) { acc1[r][0] = 0.f; acc1[r][1] = 0.f; }
#pragma unroll 4
        for (int k0 = 0; k0 < 128; k0 += 4) {
            float a[4][4];
#pragma unroll
            for (int r = 0; r < 4; r++)
                *reinterpret_cast<float4*>(a[r]) =
                    *reinterpret_cast<const float4*>(&hs[rg4 + r][k0]);
#pragma unroll
            for (int kk = 0; kk < 4; kk++) {
                float2 w = *reinterpret_cast<const float2*>(&W1b[(k0 + kk) * DD + c2]);
#pragma unroll
                for (int r = 0; r < 4; r++) {
                    acc1[r][0] = fmaf(a[r][kk], w.x, acc1[r][0]);
                    acc1[r][1] = fmaf(a[r][kk], w.y, acc1[r][1]);
                }
            }
        }
        // Us = relu(acc1 + b1)
        {
            float bb0 = b1[c0 + c2], bb1 = b1[c0 + c2 + 1];
#pragma unroll
            for (int r = 0; r < 4; r++) {
                float2 u;
                u.x = fmaxf(acc1[r][0] + bb0, 0.0f);
                u.y = fmaxf(acc1[r][1] + bb1, 0.0f);
                *reinterpret_cast<float2*>(&Us[rg4 + r][c2]) = u;
            }
        }

        // prefetch W1(ci+1) into the other buffer (overlaps ff2)
        if (ci < 3) {
            uint32_t dst = w1s + (uint32_t)(((ci + 1) & 1) * 16384) * 4;
            const float* src = W1 + c0 + 128;
#pragma unroll
            for (int i = 0; i < 16; i++) {
                int t16 = tid + i * 256;
                int k = t16 >> 5, c4 = (t16 & 31) << 2;
                cp_async16(dst + (uint32_t)(k * DD + c4) * 4, src + k * HH + c4);
            }
            cp_commit();
        }

        if (ci < 3) cp_wait1(); else cp_wait0();   // W2(ci) ready
        __syncthreads();                            // + Us visible

        // ---- ff2 partial: acc2 += Us @ W2c ----
#pragma unroll 4
        for (int k0 = 0; k0 < 128; k0 += 4) {
            float a[4][4];
#pragma unroll
            for (int r = 0; r < 4; r++)
                *reinterpret_cast<float4*>(a[r]) =
                    *reinterpret_cast<const float4*>(&Us[rg4 + r][k0]);
#pragma unroll
            for (int kk = 0; kk < 4; kk++) {
                float2 w = *reinterpret_cast<const float2*>(&W2c[k0 + kk][c2]);
#pragma unroll
                for (int r = 0; r < 4; r++) {
                    acc2[r][0] = fmaf(a[r][kk], w.x, acc2[r][0]);
                    acc2[r][1] = fmaf(a[r][kk], w.y, acc2[r][1]);
                }
            }
        }
        __syncthreads();    // W2c fully consumed

        // prefetch W2(ci+1) (overlaps next ff1)
        if (ci < 3) {
            const float* src = W2 + (c0 + 128) * DD;
#pragma unroll
            for (int i = 0; i < 16; i++) {
                int t16 = tid + i * 256;
                int k = t16 >> 5, c4 = (t16 & 31) << 2;
                cp_async16(w2s + (uint32_t)(k * DD + c4) * 4, src + k * DD + c4);
            }
            cp_commit();
        }
    }

    // epilogue: +b2 +residual (hs), LN (warp partial + 2-way combine)
    float v[4][2], s[4], q[4];
    float b20 = b2[c2], b21 = b2[c2 + 1];
#pragma unroll
    for (int r = 0; r < 4; r++) {
        v[r][0] = acc2[r][0] + b20 + hs[rg4 + r][c2];
        v[r][1] = acc2[r][1] + b21 + hs[rg4 + r][c2 + 1];
        s[r] = v[r][0] + v[r][1];
        q[r] = v[r][0] * v[r][0] + v[r][1] * v[r][1];
    }
#pragma unroll
    for (int o = 16; o > 0; o >>= 1)
#pragma unroll
        for (int r = 0; r < 4; r++) {
            s[r] += __shfl_xor_sync(0xffffffffu, s[r], o);
            q[r] += __shfl_xor_sync(0xffffffffu, q[r], o);
        }
    if (lane == 0)
#pragma unroll
        for (int r = 0; r < 4; r++) { lnS[cg][rg4 + r] = s[r]; lnQ[cg][rg4 + r] = q[r]; }
    __syncthreads();
    float g0 = gf[c2], g1 = gf[c2 + 1], e0 = bgf[c2], e1 = bgf[c2 + 1];
#pragma unroll
    for (int r = 0; r < 4; r++) {
        float S = lnS[0][rg4 + r] + lnS[1][rg4 + r];
        float Q = lnQ[0][rg4 + r] + lnQ[1][rg4 + r];
        float mean = S * (1.0f / DD);
        float rstd = rsqrtf(Q * (1.0f / DD) - mean * mean + LN_EPS);
        float2 o;
        o.x = (v[r][0] - mean) * rstd * g0 + e0;
        o.y = (v[r][1] - mean) * rstd * g1 + e1;
        int row = row0 + rg4 + r;
        if (FINAL) *reinterpret_cast<float2*>(&out[row * DD + c2]) = o;
        else       *reinterpret_cast<float2*>(&g_h[row * DD + c2]) = o;
    }
}

extern "C" void kernel_launch(void* const* d_in, const int* in_sizes, int n_in,
                              void* d_out, int out_size) {
    const float* x   = (const float*)d_in[0];   // (8,256,2)
    const float* We  = (const float*)d_in[1];   // (2,128)
    const float* be  = (const float*)d_in[2];
    const float* ge  = (const float*)d_in[3];
    const float* bge = (const float*)d_in[4];
    const float* Wp  = (const float*)d_in[5];   // (2,256,128)
    const float* bp  = (const float*)d_in[6];
    const float* gp  = (const float*)d_in[7];
    const float* bgp = (const float*)d_in[8];
    const float* W1  = (const float*)d_in[9];   // (2,128,512)
    const float* b1  = (const float*)d_in[10];
    const float* W2  = (const float*)d_in[11];  // (2,512,128)
    const float* b2  = (const float*)d_in[12];
    const float* gf  = (const float*)d_in[13];
    const float* bgf = (const float*)d_in[14];
    float* out = (float*)d_out;                 // (8,256,128) fp32

    cudaFuncSetAttribute(pool_gemm_ln_kernel,
                         cudaFuncAttributeMaxDynamicSharedMemorySize, POOL_SMEM);
    cudaFuncSetAttribute(ff_fused_kernel<false>,
                         cudaFuncAttributeMaxDynamicSharedMemorySize, FF_SMEM);
    cudaFuncSetAttribute(ff_fused_kernel<true>,
                         cudaFuncAttributeMaxDynamicSharedMemorySize, FF_SMEM);

    embed_ln_kernel<<<T_TOK, 128>>>(x, We, be, ge, bge);

    for (int i = 0; i < 2; i++) {
        stats_kernel<<<NB, dim3(128, 4)>>>();

        pool_gemm_ln_kernel<<<T_TOK / 16, 256, POOL_SMEM>>>(
            Wp + i * 2 * DD * DD, bp + i * DD, gp + i * DD, bgp + i * DD);

        if (i == 1)
            ff_fused_kernel<true><<<T_TOK / 16, 256, FF_SMEM>>>(
                W1 + i * DD * HH, b1 + i * HH, W2 + i * HH * DD, b2 + i * DD,
                gf + i * DD, bgf + i * DD, out);
        else
            ff_fused_kernel<false><<<T_TOK / 16, 256, FF_SMEM>>>(
                W1 + i * DD * HH, b1 + i * HH, W2 + i * HH * DD, b2 + i * DD,
                gf + i * DD, bgf + i * DD, nullptr);
    }
}